// round 1
// baseline (speedup 1.0000x reference)
#include <cuda_runtime.h>
#include <cstdint>

#define N_NODES 30000
#define N_EDGES 480000
#define DIN     1000
#define NH      8
#define FH      32
#define HF      256   // NH*FH
#define DEMB    64
#define NEG     0.2f

// ---------------- scratch (device globals; no allocation allowed) ----------
__device__ float g_h   [(size_t)N_NODES*HF];   // x@W
__device__ float g_as  [N_NODES*NH];
__device__ float g_ad  [N_NODES*NH];
__device__ int   g_deg [N_NODES];
__device__ int   g_off [N_NODES+1];
__device__ int   g_cur [N_NODES];
__device__ int   g_srcs[N_EDGES];              // src ids sorted by dst
__device__ float g_gat [(size_t)N_NODES*HF];   // relu(GAT out + bias)
__device__ float g_d   [(size_t)N_NODES*FH];   // decoder hidden

// ---------------- generic guarded SGEMM ------------------------------------
// C[M,N] = (relu?)(A[M,K] @ B[K,N] (+ bias[N]))
template<int BM,int BN,int BK,int TM,int TN,int RELU,int BIAS>
__global__ void sgemm_kernel(const float* __restrict__ A,
                             const float* __restrict__ B,
                             const float* __restrict__ bias,
                             float* __restrict__ C,
                             int M, int N, int K)
{
    __shared__ float As[BK][BM+4];
    __shared__ float Bs[BK][BN+4];
    const int t  = threadIdx.x;                 // 256 threads
    const int m0 = blockIdx.y*BM, n0 = blockIdx.x*BN;
    const int tx = t % (BN/TN), ty = t / (BN/TN);

    float acc[TM][TN];
    #pragma unroll
    for (int i=0;i<TM;i++)
        #pragma unroll
        for (int j=0;j<TN;j++) acc[i][j]=0.f;

    for (int k0=0;k0<K;k0+=BK) {
        #pragma unroll
        for (int i=0;i<(BM*BK)/256;i++){
            int lin = t + 256*i;
            int r = lin / BK, c = lin % BK;
            float v=0.f;
            if (m0+r<M && k0+c<K) v = A[(size_t)(m0+r)*K + k0+c];
            As[c][r]=v;
        }
        #pragma unroll
        for (int i=0;i<(BN*BK)/256;i++){
            int lin = t + 256*i;
            int r = lin / BN, c = lin % BN;
            float v=0.f;
            if (k0+r<K && n0+c<N) v = B[(size_t)(k0+r)*N + n0+c];
            Bs[r][c]=v;
        }
        __syncthreads();
        #pragma unroll
        for (int k=0;k<BK;k++){
            float ra[TM], rb[TN];
            #pragma unroll
            for (int i=0;i<TM;i++) ra[i]=As[k][ty*TM+i];
            #pragma unroll
            for (int j=0;j<TN;j++) rb[j]=Bs[k][tx*TN+j];
            #pragma unroll
            for (int i=0;i<TM;i++)
                #pragma unroll
                for (int j=0;j<TN;j++) acc[i][j] += ra[i]*rb[j];
        }
        __syncthreads();
    }
    #pragma unroll
    for (int i=0;i<TM;i++){
        int m = m0+ty*TM+i;
        if (m>=M) continue;
        #pragma unroll
        for (int j=0;j<TN;j++){
            int n = n0+tx*TN+j;
            if (n>=N) continue;
            float v = acc[i][j];
            if (BIAS) v += bias[n];
            if (RELU) v = fmaxf(v,0.f);
            C[(size_t)m*N+n] = v;
        }
    }
}

// ---------------- per-node attention logits a_s, a_d ------------------------
__global__ void att_kernel(const float* __restrict__ att_src,
                           const float* __restrict__ att_dst)
{
    int warp = (blockIdx.x*blockDim.x + threadIdx.x) >> 5;
    int lane = threadIdx.x & 31;
    if (warp >= N_NODES) return;
    const float* hr = g_h + (size_t)warp*HF;
    #pragma unroll
    for (int h=0;h<NH;h++){
        float hv = hr[h*FH+lane];
        float vs = hv*att_src[h*FH+lane];
        float vd = hv*att_dst[h*FH+lane];
        #pragma unroll
        for (int s=16;s>0;s>>=1){
            vs += __shfl_down_sync(0xffffffffu,vs,s);
            vd += __shfl_down_sync(0xffffffffu,vd,s);
        }
        if (lane==0){ g_as[warp*NH+h]=vs; g_ad[warp*NH+h]=vd; }
    }
}

// ---------------- CSR build --------------------------------------------------
__global__ void zero_deg_kernel(){
    int i = blockIdx.x*blockDim.x+threadIdx.x;
    if (i<N_NODES) g_deg[i]=0;
}
__global__ void count_kernel(const int* __restrict__ ei){
    int e = blockIdx.x*blockDim.x+threadIdx.x;
    if (e<N_EDGES) atomicAdd(&g_deg[ei[N_EDGES+e]],1);
}
__global__ void scan_kernel(){
    __shared__ int sm[1024];
    int t = threadIdx.x;
    const int CH = (N_NODES + 1023)/1024;   // 30
    int base = t*CH;
    int s=0;
    for (int i=0;i<CH;i++){ int idx=base+i; if(idx<N_NODES) s+=g_deg[idx]; }
    sm[t]=s; __syncthreads();
    for (int st=1; st<1024; st<<=1){
        int v = (t>=st)? sm[t-st]:0;
        __syncthreads();
        sm[t]+=v;
        __syncthreads();
    }
    int run = sm[t]-s;                      // exclusive prefix
    for (int i=0;i<CH;i++){
        int idx=base+i;
        if (idx<N_NODES){ g_off[idx]=run; g_cur[idx]=run; run+=g_deg[idx]; }
    }
    if (t==1023) g_off[N_NODES]=sm[1023];
}
__global__ void scatter_kernel(const int* __restrict__ ei){
    int e = blockIdx.x*blockDim.x+threadIdx.x;
    if (e<N_EDGES){
        int d = ei[N_EDGES+e];
        int p = atomicAdd(&g_cur[d],1);
        g_srcs[p] = ei[e];
    }
}

// ---------------- fused softmax + aggregate per dst node --------------------
// block = 256 threads, thread t owns output feature t (head = t/32)
__global__ void agg_kernel(const float* __restrict__ bias_gat)
{
    const int node = blockIdx.x;
    const int t    = threadIdx.x;
    const int head = t >> 5;

    __shared__ int   s_src[64];
    __shared__ float s_p[64][NH];
    __shared__ float s_m[NH];
    __shared__ float s_ps[NH];
    __shared__ float s_den[NH];
    __shared__ float wmax[8][NH];
    __shared__ float red[256];

    const int off = g_off[node];
    const int deg = g_off[node+1]-off;

    float adv[NH];
    #pragma unroll
    for (int h=0;h<NH;h++) adv[h]=g_ad[node*NH+h];

    // ---- pass 1: max logit per head (self loop included) ----
    float lm[NH];
    #pragma unroll
    for (int h=0;h<NH;h++){
        float l = g_as[node*NH+h] + adv[h];
        lm[h] = (l>0.f) ? l : NEG*l;
    }
    for (int e=t; e<deg; e+=256){
        int s = g_srcs[off+e];
        #pragma unroll
        for (int h=0;h<NH;h++){
            float l = g_as[s*NH+h] + adv[h];
            l = (l>0.f) ? l : NEG*l;
            lm[h] = fmaxf(lm[h], l);
        }
    }
    #pragma unroll
    for (int h=0;h<NH;h++){
        float v = lm[h];
        #pragma unroll
        for (int st=16;st>0;st>>=1) v = fmaxf(v, __shfl_xor_sync(0xffffffffu,v,st));
        lm[h]=v;
    }
    if ((t&31)==0){
        #pragma unroll
        for (int h=0;h<NH;h++) wmax[t>>5][h]=lm[h];
    }
    __syncthreads();
    if (t<NH){
        float m = wmax[0][t];
        #pragma unroll
        for (int w=1;w<8;w++) m = fmaxf(m, wmax[w][t]);
        s_m[t]=m;
        float l = g_as[node*NH+t] + g_ad[node*NH+t];
        l = (l>0.f) ? l : NEG*l;
        float p = expf(l-m);
        s_ps[t]=p; s_den[t]=p;
    }
    __syncthreads();

    // ---- pass 2: chunked p computation + feature aggregation ----
    float acc  = g_h[(size_t)node*HF + t] * s_ps[head];   // self loop message
    float dloc = 0.f;
    for (int c0=0; c0<deg; c0+=64){
        int nc = min(64, deg-c0);
        if (t<nc) s_src[t] = g_srcs[off+c0+t];
        __syncthreads();
        for (int pr=t; pr<nc*NH; pr+=256){
            int e = pr>>3, h = pr&7;
            int s = s_src[e];
            float l = g_as[s*NH+h] + adv[h];
            l = (l>0.f) ? l : NEG*l;
            float p = expf(l - s_m[h]);
            s_p[e][h]=p;
            dloc += p;           // this thread's (t&7)-head partial
        }
        __syncthreads();
        #pragma unroll 4
        for (int e=0;e<nc;e++){
            acc += g_h[(size_t)s_src[e]*HF + t] * s_p[e][head];
        }
        __syncthreads();
    }

    // ---- denominator reduce (threads sharing t&7 hold partials of head t&7)
    red[t]=dloc; __syncthreads();
    if (t<NH){
        float d = s_den[t];
        #pragma unroll
        for (int j=0;j<32;j++) d += red[t+8*j];
        s_den[t]=d;
    }
    __syncthreads();

    float v = acc / s_den[head] + bias_gat[t];
    g_gat[(size_t)node*HF + t] = fmaxf(v, 0.f);
}

// ---------------- launch -----------------------------------------------------
extern "C" void kernel_launch(void* const* d_in, const int* in_sizes, int n_in,
                              void* d_out, int out_size)
{
    const float* x        = (const float*)d_in[0];
    const int*   ei       = (const int*)  d_in[1];
    // d_in[2] = edge_weight (unused by reference)
    const float* W        = (const float*)d_in[3];
    const float* att_src  = (const float*)d_in[4];
    const float* att_dst  = (const float*)d_in[5];
    const float* bias_gat = (const float*)d_in[6];
    const float* emb_W    = (const float*)d_in[7];
    const float* emb_b    = (const float*)d_in[8];
    const float* dec_W1   = (const float*)d_in[9];
    const float* dec_b1   = (const float*)d_in[10];
    const float* dec_W2   = (const float*)d_in[11];
    const float* dec_b2   = (const float*)d_in[12];

    float* recon = (float*)d_out;                              // [N, DIN]
    float* z     = (float*)d_out + (size_t)N_NODES*DIN;        // [N, DEMB]

    float *hp, *gatp, *dp;
    cudaGetSymbolAddress((void**)&hp,   g_h);
    cudaGetSymbolAddress((void**)&gatp, g_gat);
    cudaGetSymbolAddress((void**)&dp,   g_d);

    const int MB = (N_NODES + 127)/128;   // 235

    // 1) h = x @ W                      [30000,1000] x [1000,256]
    sgemm_kernel<128,64,16,8,4,0,0><<<dim3(4,MB),256>>>(x, W, nullptr, hp,
                                                        N_NODES, HF, DIN);
    // 2) a_s, a_d
    att_kernel<<<(N_NODES*32+255)/256,256>>>(att_src, att_dst);
    // 3) CSR by dst
    zero_deg_kernel<<<(N_NODES+255)/256,256>>>();
    count_kernel  <<<(N_EDGES+255)/256,256>>>(ei);
    scan_kernel   <<<1,1024>>>();
    scatter_kernel<<<(N_EDGES+255)/256,256>>>(ei);
    // 4) attention softmax + aggregate + bias + relu
    agg_kernel<<<N_NODES,256>>>(bias_gat);
    // 5) z = gat @ emb_W + emb_b       [30000,256] x [256,64]
    sgemm_kernel<128,64,16,8,4,0,1><<<dim3(1,MB),256>>>(gatp, emb_W, emb_b, z,
                                                        N_NODES, DEMB, HF);
    // 6) d = relu(z @ dec_W1 + dec_b1) [30000,64] x [64,32]
    sgemm_kernel<128,64,16,8,4,1,1><<<dim3(1,MB),256>>>(z, dec_W1, dec_b1, dp,
                                                        N_NODES, FH, DEMB);
    // 7) recon = d @ dec_W2 + dec_b2   [30000,32] x [32,1000]
    sgemm_kernel<128,64,16,8,4,0,1><<<dim3((DIN+63)/64,MB),256>>>(dp, dec_W2, dec_b2,
                                                                  recon,
                                                                  N_NODES, DIN, FH);
}

// round 4
// speedup vs baseline: 1.3217x; 1.3217x over previous
#include <cuda_runtime.h>
#include <cuda_bf16.h>
#include <cstdint>

#define N_NODES 30000
#define N_PAD   30080      // 235 * 128
#define N_EDGES 480000
#define DIN     1000
#define KSEC    1024       // padded section K
#define KTOT    3072       // 3 sections
#define NH      8
#define FH      32
#define HF      256        // NH*FH
#define DEMB    64
#define NEG     0.2f

// ---------------- scratch (device globals; no allocation allowed) ----------
__device__ __nv_bfloat16 g_xhi[(size_t)N_PAD*KSEC];
__device__ __nv_bfloat16 g_xlo[(size_t)N_PAD*KSEC];
__device__ __nv_bfloat16 g_wB [(size_t)HF*KTOT];    // B' [N=256][K=3072] K-major
__device__ float g_h   [(size_t)N_NODES*HF];   // x@W
__device__ float g_as  [N_NODES*NH];
__device__ float g_ad  [N_NODES*NH];
__device__ int   g_deg [N_NODES];
__device__ int   g_off [N_NODES+1];
__device__ int   g_cur [N_NODES];
__device__ int   g_srcs[N_EDGES];              // src ids sorted by dst
__device__ float g_gat [(size_t)N_NODES*HF];   // relu(GAT out + bias)
__device__ float g_d   [(size_t)N_NODES*FH];   // decoder hidden

// ======================= helpers ============================================
__device__ __forceinline__ uint32_t smem_to_u32(const void* p) {
    uint32_t a;
    asm("{ .reg .u64 t; cvta.to.shared.u64 t, %1; cvt.u32.u64 %0, t; }"
        : "=r"(a) : "l"(p));
    return a;
}
__device__ __forceinline__ void cpasync16(uint32_t saddr, const void* gp) {
    asm volatile("cp.async.cg.shared.global [%0], [%1], 16;" :: "r"(saddr), "l"(gp));
}
__device__ __forceinline__ void ldm_x4(uint32_t& r0, uint32_t& r1,
                                       uint32_t& r2, uint32_t& r3, uint32_t a) {
    asm volatile("ldmatrix.sync.aligned.m8n8.x4.shared.b16 {%0,%1,%2,%3}, [%4];"
                 : "=r"(r0), "=r"(r1), "=r"(r2), "=r"(r3) : "r"(a));
}
__device__ __forceinline__ void mma_bf16(float* c, const uint32_t* a,
                                         uint32_t b0, uint32_t b1) {
    asm volatile(
        "mma.sync.aligned.m16n8k16.row.col.f32.bf16.bf16.f32 "
        "{%0,%1,%2,%3}, {%4,%5,%6,%7}, {%8,%9}, {%0,%1,%2,%3};"
        : "+f"(c[0]), "+f"(c[1]), "+f"(c[2]), "+f"(c[3])
        : "r"(a[0]), "r"(a[1]), "r"(a[2]), "r"(a[3]), "r"(b0), "r"(b1));
}

// ======================= split / pack kernels ===============================
__global__ void split_x_kernel(const float* __restrict__ x) {
    size_t idx = (size_t)blockIdx.x * blockDim.x + threadIdx.x;
    if (idx >= (size_t)N_PAD * KSEC) return;
    int r = (int)(idx >> 10);
    int c = (int)(idx & 1023);
    float v = (r < N_NODES && c < DIN) ? x[(size_t)r * DIN + c] : 0.f;
    __nv_bfloat16 hi = __float2bfloat16(v);
    g_xhi[idx] = hi;
    g_xlo[idx] = __float2bfloat16(v - __bfloat162float(hi));
}
__global__ void build_wB_kernel(const float* __restrict__ W) {
    int idx = blockIdx.x * blockDim.x + threadIdx.x;       // over 256*3072
    if (idx >= HF * KTOT) return;
    int n  = idx / KTOT;
    int kk = idx % KTOT;
    int s  = kk >> 10;
    int k  = kk & 1023;
    float v = (k < DIN) ? W[(size_t)k * HF + n] : 0.f;
    __nv_bfloat16 hi = __float2bfloat16(v);
    g_wB[idx] = (s == 2) ? __float2bfloat16(v - __bfloat162float(hi)) : hi;
}

// ======================= bf16 mma.sync GEMM1 ================================
// C[30080,256] = A'[30080,3072]bf16 @ B'[3072,256]bf16 (B stored [256][3072])
// BM=128 BN=128 BK=32, 256 threads, 8 warps (4 m x 2 n), warp tile 32x64.
#define BKC  32
#define LDSM 40           // BKC + 8 pad elements (80B row stride)
#define NCH  96           // 3072/32

__global__ void __launch_bounds__(256) gemm1_mma_kernel() {
    __shared__ __nv_bfloat16 sA[2][128][LDSM];
    __shared__ __nv_bfloat16 sB[2][128][LDSM];
    const int t    = threadIdx.x;
    const int lane = t & 31;
    const int wid  = t >> 5;
    const int wm   = (wid & 3) * 32;
    const int wn   = (wid >> 2) * 64;
    const int m0   = blockIdx.y * 128;
    const int n0   = blockIdx.x * 128;

    float acc[2][8][4];
    #pragma unroll
    for (int i = 0; i < 2; i++)
        #pragma unroll
        for (int j = 0; j < 8; j++)
            #pragma unroll
            for (int q = 0; q < 4; q++) acc[i][j][q] = 0.f;

    // A-frag ldmatrix row/col (within warp tile)
    const int a_r = (lane & 7) + ((lane >> 3) & 1) * 8;
    const int a_c = (lane >> 4) * 8;
    // B-frag ldmatrix row/col
    const int b_r = ((lane >> 4) & 1) * 8 + (lane & 7);
    const int b_c = ((lane >> 3) & 1) * 8;

    // Each stage tile: 128 rows x 32 cols bf16 = 512 x 16B chunks per operand.
    // 256 threads x 2 iters x 16B covers all 512 chunks.
    auto load_stage = [&](int s, int c) {
        const int kp  = c * BKC;
        const int sec = kp >> 10;
        const int ko  = kp & 1023;
        const __nv_bfloat16* Abase = ((sec == 1) ? g_xlo : g_xhi)
                                     + (size_t)m0 * KSEC + ko;
        const __nv_bfloat16* Bbase = g_wB + (size_t)n0 * KTOT + kp;
        #pragma unroll
        for (int i = 0; i < 2; i++) {
            int u  = t + 256 * i;
            int r  = u >> 2;            // 0..127
            int ch = (u & 3) * 8;       // element offset 0,8,16,24
            cpasync16(smem_to_u32(&sA[s][r][ch]), Abase + (size_t)r * KSEC + ch);
            cpasync16(smem_to_u32(&sB[s][r][ch]), Bbase + (size_t)r * KTOT + ch);
        }
    };

    load_stage(0, 0);
    asm volatile("cp.async.commit_group;" ::: "memory");
    load_stage(1, 1);
    asm volatile("cp.async.commit_group;" ::: "memory");

    for (int c = 0; c < NCH; c++) {
        const int s = c & 1;
        asm volatile("cp.async.wait_group 1;" ::: "memory");
        __syncthreads();

        #pragma unroll
        for (int ks = 0; ks < 2; ks++) {
            const int kb = ks * 16;
            uint32_t a[2][4];
            #pragma unroll
            for (int mt = 0; mt < 2; mt++) {
                uint32_t ad = smem_to_u32(&sA[s][wm + mt * 16 + a_r][kb + a_c]);
                ldm_x4(a[mt][0], a[mt][1], a[mt][2], a[mt][3], ad);
            }
            #pragma unroll
            for (int nt4 = 0; nt4 < 4; nt4++) {
                uint32_t b0, b1, b2, b3;
                uint32_t bd = smem_to_u32(&sB[s][wn + nt4 * 16 + b_r][kb + b_c]);
                ldm_x4(b0, b1, b2, b3, bd);
                #pragma unroll
                for (int mt = 0; mt < 2; mt++) {
                    mma_bf16(acc[mt][nt4 * 2 + 0], a[mt], b0, b1);
                    mma_bf16(acc[mt][nt4 * 2 + 1], a[mt], b2, b3);
                }
            }
        }
        __syncthreads();
        if (c + 2 < NCH) load_stage(s, c + 2);
        asm volatile("cp.async.commit_group;" ::: "memory");
    }

    // epilogue: write C fragments to g_h
    #pragma unroll
    for (int mt = 0; mt < 2; mt++) {
        const int r0 = m0 + wm + mt * 16 + (lane >> 2);
        #pragma unroll
        for (int nt = 0; nt < 8; nt++) {
            const int cc = n0 + wn + nt * 8 + (lane & 3) * 2;
            if (r0 < N_NODES)
                *(float2*)&g_h[(size_t)r0 * HF + cc] =
                    make_float2(acc[mt][nt][0], acc[mt][nt][1]);
            if (r0 + 8 < N_NODES)
                *(float2*)&g_h[(size_t)(r0 + 8) * HF + cc] =
                    make_float2(acc[mt][nt][2], acc[mt][nt][3]);
        }
    }
}

// ---------------- generic guarded SGEMM (small GEMMs) -----------------------
template<int BM,int BN,int BK,int TM,int TN,int RELU,int BIAS>
__global__ void sgemm_kernel(const float* __restrict__ A,
                             const float* __restrict__ B,
                             const float* __restrict__ bias,
                             float* __restrict__ C,
                             int M, int N, int K)
{
    __shared__ float As[BK][BM+4];
    __shared__ float Bs[BK][BN+4];
    const int t  = threadIdx.x;                 // 256 threads
    const int m0 = blockIdx.y*BM, n0 = blockIdx.x*BN;
    const int tx = t % (BN/TN), ty = t / (BN/TN);

    float acc[TM][TN];
    #pragma unroll
    for (int i=0;i<TM;i++)
        #pragma unroll
        for (int j=0;j<TN;j++) acc[i][j]=0.f;

    for (int k0=0;k0<K;k0+=BK) {
        #pragma unroll
        for (int i=0;i<(BM*BK)/256;i++){
            int lin = t + 256*i;
            int r = lin / BK, c = lin % BK;
            float v=0.f;
            if (m0+r<M && k0+c<K) v = A[(size_t)(m0+r)*K + k0+c];
            As[c][r]=v;
        }
        #pragma unroll
        for (int i=0;i<(BN*BK)/256;i++){
            int lin = t + 256*i;
            int r = lin / BN, c = lin % BN;
            float v=0.f;
            if (k0+r<K && n0+c<N) v = B[(size_t)(k0+r)*N + n0+c];
            Bs[r][c]=v;
        }
        __syncthreads();
        #pragma unroll
        for (int k=0;k<BK;k++){
            float ra[TM], rb[TN];
            #pragma unroll
            for (int i=0;i<TM;i++) ra[i]=As[k][ty*TM+i];
            #pragma unroll
            for (int j=0;j<TN;j++) rb[j]=Bs[k][tx*TN+j];
            #pragma unroll
            for (int i=0;i<TM;i++)
                #pragma unroll
                for (int j=0;j<TN;j++) acc[i][j] += ra[i]*rb[j];
        }
        __syncthreads();
    }
    #pragma unroll
    for (int i=0;i<TM;i++){
        int m = m0+ty*TM+i;
        if (m>=M) continue;
        #pragma unroll
        for (int j=0;j<TN;j++){
            int n = n0+tx*TN+j;
            if (n>=N) continue;
            float v = acc[i][j];
            if (BIAS) v += bias[n];
            if (RELU) v = fmaxf(v,0.f);
            C[(size_t)m*N+n] = v;
        }
    }
}

// ---------------- per-node attention logits a_s, a_d ------------------------
__global__ void att_kernel(const float* __restrict__ att_src,
                           const float* __restrict__ att_dst)
{
    int warp = (blockIdx.x*blockDim.x + threadIdx.x) >> 5;
    int lane = threadIdx.x & 31;
    if (warp >= N_NODES) return;
    const float* hr = g_h + (size_t)warp*HF;
    #pragma unroll
    for (int h=0;h<NH;h++){
        float hv = hr[h*FH+lane];
        float vs = hv*att_src[h*FH+lane];
        float vd = hv*att_dst[h*FH+lane];
        #pragma unroll
        for (int s=16;s>0;s>>=1){
            vs += __shfl_down_sync(0xffffffffu,vs,s);
            vd += __shfl_down_sync(0xffffffffu,vd,s);
        }
        if (lane==0){ g_as[warp*NH+h]=vs; g_ad[warp*NH+h]=vd; }
    }
}

// ---------------- CSR build --------------------------------------------------
__global__ void zero_deg_kernel(){
    int i = blockIdx.x*blockDim.x+threadIdx.x;
    if (i<N_NODES) g_deg[i]=0;
}
__global__ void count_kernel(const int* __restrict__ ei){
    int e = blockIdx.x*blockDim.x+threadIdx.x;
    if (e<N_EDGES) atomicAdd(&g_deg[ei[N_EDGES+e]],1);
}
__global__ void scan_kernel(){
    __shared__ int sm[1024];
    int t = threadIdx.x;
    const int CH = (N_NODES + 1023)/1024;   // 30
    int base = t*CH;
    int s=0;
    for (int i=0;i<CH;i++){ int idx=base+i; if(idx<N_NODES) s+=g_deg[idx]; }
    sm[t]=s; __syncthreads();
    for (int st=1; st<1024; st<<=1){
        int v = (t>=st)? sm[t-st]:0;
        __syncthreads();
        sm[t]+=v;
        __syncthreads();
    }
    int run = sm[t]-s;                      // exclusive prefix
    for (int i=0;i<CH;i++){
        int idx=base+i;
        if (idx<N_NODES){ g_off[idx]=run; g_cur[idx]=run; run+=g_deg[idx]; }
    }
    if (t==1023) g_off[N_NODES]=sm[1023];
}
__global__ void scatter_kernel(const int* __restrict__ ei){
    int e = blockIdx.x*blockDim.x+threadIdx.x;
    if (e<N_EDGES){
        int d = ei[N_EDGES+e];
        int p = atomicAdd(&g_cur[d],1);
        g_srcs[p] = ei[e];
    }
}

// ---------------- fused softmax + aggregate per dst node --------------------
__global__ void agg_kernel(const float* __restrict__ bias_gat)
{
    const int node = blockIdx.x;
    const int t    = threadIdx.x;
    const int head = t >> 5;

    __shared__ int   s_src[64];
    __shared__ float s_p[64][NH];
    __shared__ float s_m[NH];
    __shared__ float s_ps[NH];
    __shared__ float s_den[NH];
    __shared__ float wmax[8][NH];
    __shared__ float red[256];

    const int off = g_off[node];
    const int deg = g_off[node+1]-off;

    float adv[NH];
    #pragma unroll
    for (int h=0;h<NH;h++) adv[h]=g_ad[node*NH+h];

    float lm[NH];
    #pragma unroll
    for (int h=0;h<NH;h++){
        float l = g_as[node*NH+h] + adv[h];
        lm[h] = (l>0.f) ? l : NEG*l;
    }
    for (int e=t; e<deg; e+=256){
        int s = g_srcs[off+e];
        #pragma unroll
        for (int h=0;h<NH;h++){
            float l = g_as[s*NH+h] + adv[h];
            l = (l>0.f) ? l : NEG*l;
            lm[h] = fmaxf(lm[h], l);
        }
    }
    #pragma unroll
    for (int h=0;h<NH;h++){
        float v = lm[h];
        #pragma unroll
        for (int st=16;st>0;st>>=1) v = fmaxf(v, __shfl_xor_sync(0xffffffffu,v,st));
        lm[h]=v;
    }
    if ((t&31)==0){
        #pragma unroll
        for (int h=0;h<NH;h++) wmax[t>>5][h]=lm[h];
    }
    __syncthreads();
    if (t<NH){
        float m = wmax[0][t];
        #pragma unroll
        for (int w=1;w<8;w++) m = fmaxf(m, wmax[w][t]);
        s_m[t]=m;
        float l = g_as[node*NH+t] + g_ad[node*NH+t];
        l = (l>0.f) ? l : NEG*l;
        float p = expf(l-m);
        s_ps[t]=p; s_den[t]=p;
    }
    __syncthreads();

    float acc  = g_h[(size_t)node*HF + t] * s_ps[head];   // self loop message
    float dloc = 0.f;
    for (int c0=0; c0<deg; c0+=64){
        int nc = min(64, deg-c0);
        if (t<nc) s_src[t] = g_srcs[off+c0+t];
        __syncthreads();
        for (int pr=t; pr<nc*NH; pr+=256){
            int e = pr>>3, h = pr&7;
            int s = s_src[e];
            float l = g_as[s*NH+h] + adv[h];
            l = (l>0.f) ? l : NEG*l;
            float p = expf(l - s_m[h]);
            s_p[e][h]=p;
            dloc += p;
        }
        __syncthreads();
        #pragma unroll 4
        for (int e=0;e<nc;e++){
            acc += g_h[(size_t)s_src[e]*HF + t] * s_p[e][head];
        }
        __syncthreads();
    }

    red[t]=dloc; __syncthreads();
    if (t<NH){
        float d = s_den[t];
        #pragma unroll
        for (int j=0;j<32;j++) d += red[t+8*j];
        s_den[t]=d;
    }
    __syncthreads();

    float v = acc / s_den[head] + bias_gat[t];
    g_gat[(size_t)node*HF + t] = fmaxf(v, 0.f);
}

// ---------------- launch -----------------------------------------------------
extern "C" void kernel_launch(void* const* d_in, const int* in_sizes, int n_in,
                              void* d_out, int out_size)
{
    const float* x        = (const float*)d_in[0];
    const int*   ei       = (const int*)  d_in[1];
    const float* W        = (const float*)d_in[3];
    const float* att_src  = (const float*)d_in[4];
    const float* att_dst  = (const float*)d_in[5];
    const float* bias_gat = (const float*)d_in[6];
    const float* emb_W    = (const float*)d_in[7];
    const float* emb_b    = (const float*)d_in[8];
    const float* dec_W1   = (const float*)d_in[9];
    const float* dec_b1   = (const float*)d_in[10];
    const float* dec_W2   = (const float*)d_in[11];
    const float* dec_b2   = (const float*)d_in[12];

    float* recon = (float*)d_out;                              // [N, DIN]
    float* z     = (float*)d_out + (size_t)N_NODES*DIN;        // [N, DEMB]

    float *gatp, *dp;
    cudaGetSymbolAddress((void**)&gatp, g_gat);
    cudaGetSymbolAddress((void**)&dp,   g_d);

    const int MB = (N_NODES + 127)/128;   // 235

    // 0) bf16 3-split operand prep
    split_x_kernel<<<(int)(((size_t)N_PAD*KSEC + 255)/256), 256>>>(x);
    build_wB_kernel<<<(HF*KTOT + 255)/256, 256>>>(W);
    // 1) h = x @ W via mma.sync bf16x3   [30000,1000] x [1000,256]
    gemm1_mma_kernel<<<dim3(2, MB), 256>>>();
    // 2) a_s, a_d
    att_kernel<<<(N_NODES*32+255)/256,256>>>(att_src, att_dst);
    // 3) CSR by dst
    zero_deg_kernel<<<(N_NODES+255)/256,256>>>();
    count_kernel  <<<(N_EDGES+255)/256,256>>>(ei);
    scan_kernel   <<<1,1024>>>();
    scatter_kernel<<<(N_EDGES+255)/256,256>>>(ei);
    // 4) attention softmax + aggregate + bias + relu
    agg_kernel<<<N_NODES,256>>>(bias_gat);
    // 5) z = gat @ emb_W + emb_b       [30000,256] x [256,64]
    sgemm_kernel<128,64,16,8,4,0,1><<<dim3(1,MB),256>>>(gatp, emb_W, emb_b, z,
                                                        N_NODES, DEMB, HF);
    // 6) d = relu(z @ dec_W1 + dec_b1) [30000,64] x [64,32]
    sgemm_kernel<128,64,16,8,4,1,1><<<dim3(1,MB),256>>>(z, dec_W1, dec_b1, dp,
                                                        N_NODES, FH, DEMB);
    // 7) recon = d @ dec_W2 + dec_b2   [30000,32] x [32,1000]
    sgemm_kernel<128,64,16,8,4,0,1><<<dim3((DIN+63)/64,MB),256>>>(dp, dec_W2, dec_b2,
                                                                  recon,
                                                                  N_NODES, DIN, FH);
}